// round 4
// baseline (speedup 1.0000x reference)
#include <cuda_runtime.h>
#include <cuda_bf16.h>
#include <math.h>
#include <cstdint>

// ---------------- problem constants ----------------
#define B_    16
#define NQ    256
#define NM    1024
#define DD    768       // DRUG_DIM
#define DT    2560      // TARGET_DIM
#define H_    8
#define DH    96
#define INNER 768
#define NEGV  (-1000000.0f)
#define SCALE 0.10206207261596575f
#define OUT_ELEMS (B_*NQ*INNER)

// ---------------- device scratch (allocations forbidden) ----------------
__device__ float g_Q[B_*H_*NQ*DH];     // (b,h,n,d)
__device__ float g_K[B_*H_*NM*DH];     // (b,h,m,d)
__device__ float g_V[B_*H_*NM*DH];     // (b,h,m,d)
__device__ float g_O[B_*NQ*INNER];     // (b*n, h*96+d)
__device__ float g_X[B_*NQ*INNER];     // pre-LN

// ---------------- tf32 helpers ----------------
__device__ __forceinline__ unsigned f2t(float x) {
    unsigned r; asm("cvt.rna.tf32.f32 %0, %1;" : "=r"(r) : "f"(x)); return r;
}
__device__ __forceinline__ void splitt(float x, unsigned &hi, unsigned &lo) {
    hi = f2t(x);
    lo = f2t(x - __uint_as_float(hi));
}
__device__ __forceinline__ void mma8(float4 &c,
    unsigned a0, unsigned a1, unsigned a2, unsigned a3,
    unsigned b0, unsigned b1)
{
    asm("mma.sync.aligned.m16n8k8.row.col.f32.tf32.tf32.f32 "
        "{%0,%1,%2,%3},{%4,%5,%6,%7},{%8,%9},{%0,%1,%2,%3};"
        : "+f"(c.x), "+f"(c.y), "+f"(c.z), "+f"(c.w)
        : "r"(a0), "r"(a1), "r"(a2), "r"(a3), "r"(b0), "r"(b1));
}

// ---------------- projection GEMM: C[M,768] = A[M,KD] @ W[KD,768] ----------------
// MODE 1: remap output to (b, h, s, d)     (Q/K/V projections)
// MODE 0: row-major + bias + residual       (output projection, pre-LN)
__device__ __forceinline__ void store_remap(float* out, int seqlen, int row, int c,
                                            float v0, float v1)
{
    int b = row / seqlen, s = row % seqlen;
    int h = c / DH, d = c % DH;            // c even -> pair stays in one head
    float* p = out + (((long)(b*H_ + h)*seqlen + s)*DH + d);
    p[0] = v0; p[1] = v1;
}

template<int KD, int MODE>
__global__ void __launch_bounds__(256) gemm_proj(
    const float* __restrict__ A, const float* __restrict__ W,
    float* __restrict__ out, int seqlen,
    const float* __restrict__ bias, const float* __restrict__ resid)
{
    __shared__ float As[128*36];   // 128 rows x 32 k, stride 36 (bank-injective)
    __shared__ float Ws[32*72];    // 32 k x 64 cols, stride 72 (bank-injective)

    const int tid  = threadIdx.x;
    const int lane = tid & 31, warp = tid >> 5;
    const int g    = lane >> 2, tg = lane & 3;
    const int wr   = warp >> 1, wc = warp & 1;   // 4x2 warp grid, 32x32 each
    const long row0 = (long)blockIdx.x * 128;
    const int  col0 = blockIdx.y * 64;

    float4 acc[2][4];
    #pragma unroll
    for (int i = 0; i < 2; i++)
        #pragma unroll
        for (int j = 0; j < 4; j++) acc[i][j] = make_float4(0.f,0.f,0.f,0.f);

    for (int k0 = 0; k0 < KD; k0 += 32) {
        #pragma unroll
        for (int i = 0; i < 4; i++) {              // A tile 128x32
            int q = tid + 256*i;
            int r = q >> 3, kq = q & 7;
            *(float4*)&As[r*36 + kq*4] =
                *(const float4*)(A + (row0 + r)*(long)KD + k0 + kq*4);
        }
        #pragma unroll
        for (int i = 0; i < 2; i++) {              // W tile 32x64
            int q = tid + 256*i;
            int kk = q >> 4, c4 = q & 15;
            *(float4*)&Ws[kk*72 + c4*4] =
                *(const float4*)(W + (long)(k0 + kk)*768 + col0 + c4*4);
        }
        __syncthreads();

        #pragma unroll
        for (int kk = 0; kk < 32; kk += 8) {
            unsigned ah[2][4], al[2][4];
            #pragma unroll
            for (int i = 0; i < 2; i++) {
                const float* p = &As[(wr*32 + i*16 + g)*36 + kk + tg];
                splitt(p[0],        ah[i][0], al[i][0]);
                splitt(p[8*36],     ah[i][1], al[i][1]);
                splitt(p[4],        ah[i][2], al[i][2]);
                splitt(p[8*36+4],   ah[i][3], al[i][3]);
            }
            unsigned bh[4][2], bl[4][2];
            #pragma unroll
            for (int j = 0; j < 4; j++) {
                const float* p = &Ws[(kk + tg)*72 + wc*32 + j*8 + g];
                splitt(p[0],    bh[j][0], bl[j][0]);
                splitt(p[4*72], bh[j][1], bl[j][1]);
            }
            #pragma unroll
            for (int i = 0; i < 2; i++)
                #pragma unroll
                for (int j = 0; j < 4; j++) {
                    mma8(acc[i][j], ah[i][0],ah[i][1],ah[i][2],ah[i][3], bh[j][0],bh[j][1]);
                    mma8(acc[i][j], ah[i][0],ah[i][1],ah[i][2],ah[i][3], bl[j][0],bl[j][1]);
                    mma8(acc[i][j], al[i][0],al[i][1],al[i][2],al[i][3], bh[j][0],bh[j][1]);
                }
        }
        __syncthreads();
    }

    #pragma unroll
    for (int i = 0; i < 2; i++) {
        int ra = (int)row0 + wr*32 + i*16 + g;
        int rb = ra + 8;
        #pragma unroll
        for (int j = 0; j < 4; j++) {
            int c = col0 + wc*32 + j*8 + 2*tg;
            if constexpr (MODE == 1) {
                store_remap(out, seqlen, ra, c, acc[i][j].x, acc[i][j].y);
                store_remap(out, seqlen, rb, c, acc[i][j].z, acc[i][j].w);
            } else {
                long i0 = (long)ra*768 + c;
                long i1 = (long)rb*768 + c;
                out[i0]   = acc[i][j].x + bias[c]   + resid[i0];
                out[i0+1] = acc[i][j].y + bias[c+1] + resid[i0+1];
                out[i1]   = acc[i][j].z + bias[c]   + resid[i1];
                out[i1+1] = acc[i][j].w + bias[c+1] + resid[i1+1];
            }
        }
    }
}

// ---------------- attention kernel ----------------
#define SS  1036
#define QS  108
#define KS2 108
#define SMEM_ATT ((32*SS + 32*QS + 128*KS2)*4)

__global__ void __launch_bounds__(256) attn_kernel(
    const int* __restrict__ dmask, const int* __restrict__ pmask,
    float* __restrict__ attn_out)
{
    extern __shared__ float sm[];
    float* S  = sm;                 // 32 x SS
    float* Qs = sm + 32*SS;         // 32 x QS
    float* Ks = Qs + 32*QS;         // 128 x KS2 (K chunk, later V chunk)

    const int tid  = threadIdx.x;
    const int lane = tid & 31, warp = tid >> 5;
    const int g    = lane >> 2, tg = lane & 3;
    const int b = blockIdx.z, h = blockIdx.y, n0 = blockIdx.x * 32;
    const int wr = warp >> 2, wc = warp & 3;    // 2x4 warp grid

    const float* Qg = g_Q + ((long)(b*H_ + h)*NQ + n0)*DH;
    const float* Kg = g_K + (long)(b*H_ + h)*NM*DH;
    const float* Vg = g_V + (long)(b*H_ + h)*NM*DH;

    // Q tile 32x96
    #pragma unroll
    for (int i = 0; i < 3; i++) {
        int q = tid + 256*i;
        int r = q / 24, c4 = q % 24;
        *(float4*)&Qs[r*QS + c4*4] = *(const float4*)(Qg + r*DH + c4*4);
    }

    // ---- S = Q K^T (split-tf32) ----
    for (int mc = 0; mc < 8; mc++) {
        __syncthreads();
        #pragma unroll
        for (int i = 0; i < 12; i++) {            // K chunk 128x96
            int q = tid + 256*i;
            int r = q / 24, c4 = q % 24;
            *(float4*)&Ks[r*KS2 + c4*4] = *(const float4*)(Kg + (long)(mc*128 + r)*DH + c4*4);
        }
        __syncthreads();

        float4 acc[4];
        #pragma unroll
        for (int j = 0; j < 4; j++) acc[j] = make_float4(0.f,0.f,0.f,0.f);

        #pragma unroll
        for (int kk = 0; kk < 96; kk += 8) {
            unsigned ah[4], al[4];
            {
                const float* p = &Qs[(wr*16 + g)*QS + kk + tg];
                splitt(p[0],       ah[0], al[0]);
                splitt(p[8*QS],    ah[1], al[1]);
                splitt(p[4],       ah[2], al[2]);
                splitt(p[8*QS+4],  ah[3], al[3]);
            }
            #pragma unroll
            for (int j = 0; j < 4; j++) {
                const float* p = &Ks[(wc*32 + j*8 + g)*KS2 + kk + tg];
                unsigned bh0, bl0, bh1, bl1;
                splitt(p[0], bh0, bl0);
                splitt(p[4], bh1, bl1);
                mma8(acc[j], ah[0],ah[1],ah[2],ah[3], bh0, bh1);
                mma8(acc[j], ah[0],ah[1],ah[2],ah[3], bl0, bl1);
                mma8(acc[j], al[0],al[1],al[2],al[3], bh0, bh1);
            }
        }
        int row = wr*16 + g;
        #pragma unroll
        for (int j = 0; j < 4; j++) {
            int c = mc*128 + wc*32 + j*8 + 2*tg;
            S[row*SS + c]       = acc[j].x;
            S[row*SS + c + 1]   = acc[j].y;
            S[(row+8)*SS + c]   = acc[j].z;
            S[(row+8)*SS + c+1] = acc[j].w;
        }
    }
    __syncthreads();

    // ---- mask + softmax (warp w handles rows 4w..4w+3), write attn ----
    for (int rr = 0; rr < 4; rr++) {
        int row = warp*4 + rr;
        bool dvalid = dmask[b*NQ + n0 + row] != 0;
        float* Sr = S + row*SS;
        float vbuf[32];
        float mx = -3.0e38f;
        #pragma unroll
        for (int i = 0; i < 32; i++) {
            int col = lane + 32*i;
            float vv = Sr[col] * SCALE;
            bool valid = dvalid && (pmask[b*NM + col] != 0);
            vv = valid ? vv : NEGV;
            vbuf[i] = vv;
            mx = fmaxf(mx, vv);
        }
        #pragma unroll
        for (int o = 16; o; o >>= 1) mx = fmaxf(mx, __shfl_xor_sync(~0u, mx, o));
        float sum = 0.f;
        #pragma unroll
        for (int i = 0; i < 32; i++) {
            float p = expf(vbuf[i] - mx);
            vbuf[i] = p; sum += p;
        }
        #pragma unroll
        for (int o = 16; o; o >>= 1) sum += __shfl_xor_sync(~0u, sum, o);
        float inv = 1.0f / sum;
        float* Ag = attn_out + ((long)(b*H_ + h)*NQ + n0 + row)*NM;
        #pragma unroll
        for (int i = 0; i < 32; i++) {
            int col = lane + 32*i;
            float p = vbuf[i] * inv;
            Sr[col] = p;
            Ag[col] = p;
        }
    }
    __syncthreads();

    // ---- O = P V  (split-tf32) ----
    float4 oacc[3];
    #pragma unroll
    for (int j = 0; j < 3; j++) oacc[j] = make_float4(0.f,0.f,0.f,0.f);

    for (int mc = 0; mc < 8; mc++) {
        __syncthreads();
        #pragma unroll
        for (int i = 0; i < 12; i++) {            // V chunk 128x96 into Ks
            int q = tid + 256*i;
            int r = q / 24, c4 = q % 24;
            *(float4*)&Ks[r*KS2 + c4*4] = *(const float4*)(Vg + (long)(mc*128 + r)*DH + c4*4);
        }
        __syncthreads();

        #pragma unroll
        for (int kk = 0; kk < 128; kk += 8) {
            unsigned ah[4], al[4];
            {
                const float* p = &S[(wr*16 + g)*SS + mc*128 + kk + tg];
                splitt(p[0],       ah[0], al[0]);
                splitt(p[8*SS],    ah[1], al[1]);
                splitt(p[4],       ah[2], al[2]);
                splitt(p[8*SS+4],  ah[3], al[3]);
            }
            #pragma unroll
            for (int j = 0; j < 3; j++) {
                const float* p = &Ks[(kk + tg)*KS2 + wc*24 + j*8 + g];
                unsigned bh0, bl0, bh1, bl1;
                splitt(p[0],      bh0, bl0);
                splitt(p[4*KS2],  bh1, bl1);
                mma8(oacc[j], ah[0],ah[1],ah[2],ah[3], bh0, bh1);
                mma8(oacc[j], ah[0],ah[1],ah[2],ah[3], bl0, bl1);
                mma8(oacc[j], al[0],al[1],al[2],al[3], bh0, bh1);
            }
        }
    }

    // store O: g_O[(b*NQ + n)*INNER + h*96 + d]
    {
        int ra = wr*16 + g, rb = ra + 8;
        #pragma unroll
        for (int j = 0; j < 3; j++) {
            int c = wc*24 + j*8 + 2*tg;
            long i0 = ((long)b*NQ + n0 + ra)*INNER + h*DH + c;
            long i1 = ((long)b*NQ + n0 + rb)*INNER + h*DH + c;
            g_O[i0]   = oacc[j].x;  g_O[i0+1] = oacc[j].y;
            g_O[i1]   = oacc[j].z;  g_O[i1+1] = oacc[j].w;
        }
    }
}

// ---------------- LayerNorm: warp per row ----------------
__global__ void __launch_bounds__(256) ln_kernel(
    const float* __restrict__ X, const float* __restrict__ gamma,
    const float* __restrict__ beta, float* __restrict__ out)
{
    int row  = blockIdx.x * 8 + (threadIdx.x >> 5);
    int lane = threadIdx.x & 31;
    const float* x = X + (long)row * INNER;
    float v[24];
    float s = 0.f;
    #pragma unroll
    for (int i = 0; i < 24; i++) { v[i] = x[lane + 32*i]; s += v[i]; }
    #pragma unroll
    for (int o = 16; o; o >>= 1) s += __shfl_xor_sync(~0u, s, o);
    float mu = s * (1.0f/INNER);
    float q = 0.f;
    #pragma unroll
    for (int i = 0; i < 24; i++) { float d = v[i] - mu; q += d*d; }
    #pragma unroll
    for (int o = 16; o; o >>= 1) q += __shfl_xor_sync(~0u, q, o);
    float inv = rsqrtf(q * (1.0f/INNER) + 1e-5f);
    float* op = out + (long)row * INNER;
    #pragma unroll
    for (int i = 0; i < 24; i++) {
        int c = lane + 32*i;
        op[c] = (v[i] - mu) * inv * gamma[c] + beta[c];
    }
}

// ---------------- launch ----------------
extern "C" void kernel_launch(void* const* d_in, const int* in_sizes, int n_in,
                              void* d_out, int out_size)
{
    const float* drug   = (const float*)d_in[0];
    const float* target = (const float*)d_in[1];
    const int*   dmask  = (const int*)d_in[2];
    const int*   pmask  = (const int*)d_in[3];
    const float* Wq = (const float*)d_in[4];
    const float* Wk = (const float*)d_in[5];
    const float* Wv = (const float*)d_in[6];
    const float* Wo = (const float*)d_in[7];
    const float* bo = (const float*)d_in[8];
    const float* gamma = (const float*)d_in[9];
    const float* beta  = (const float*)d_in[10];

    float* out  = (float*)d_out;
    float* attn = out + (long)OUT_ELEMS;   // tuple (out, attn) concatenated

    float *Qp, *Kp, *Vp, *Op, *Xp;
    cudaGetSymbolAddress((void**)&Qp, g_Q);
    cudaGetSymbolAddress((void**)&Kp, g_K);
    cudaGetSymbolAddress((void**)&Vp, g_V);
    cudaGetSymbolAddress((void**)&Op, g_O);
    cudaGetSymbolAddress((void**)&Xp, g_X);

    // Q/K/V projections (remap to (b,h,s,d))
    gemm_proj<DD,1><<<dim3(B_*NQ/128, 768/64), 256>>>(drug,   Wq, Qp, NQ, nullptr, nullptr);
    gemm_proj<DT,1><<<dim3(B_*NM/128, 768/64), 256>>>(target, Wk, Kp, NM, nullptr, nullptr);
    gemm_proj<DT,1><<<dim3(B_*NM/128, 768/64), 256>>>(target, Wv, Vp, NM, nullptr, nullptr);

    // attention (scores + mask + softmax + attn out + P@V)
    cudaFuncSetAttribute(attn_kernel, cudaFuncAttributeMaxDynamicSharedMemorySize, SMEM_ATT);
    attn_kernel<<<dim3(NQ/32, H_, B_), 256, SMEM_ATT>>>(dmask, pmask, attn);

    // output projection + bias + residual
    gemm_proj<INNER,0><<<dim3(B_*NQ/128, 768/64), 256>>>(Op, Wo, Xp, NQ, bo, drug);

    // LayerNorm
    ln_kernel<<<B_*NQ/8, 256>>>(Xp, gamma, beta, out);
}

// round 14
// speedup vs baseline: 1.4600x; 1.4600x over previous
#include <cuda_runtime.h>
#include <cuda_bf16.h>
#include <math.h>
#include <cstdint>

// ---------------- problem constants ----------------
#define B_    16
#define NQ    256
#define NM    1024
#define DD    768       // DRUG_DIM
#define DT    2560      // TARGET_DIM
#define H_    8
#define DH    96
#define INNER 768
#define NEGV  (-1000000.0f)
#define SCALE 0.10206207261596575f
#define OUT_ELEMS (B_*NQ*INNER)

// ---------------- device scratch (allocations forbidden) ----------------
__device__ float g_Q[B_*H_*NQ*DH];     // (b,h,n,d)
__device__ float g_K[B_*H_*NM*DH];     // (b,h,m,d)
__device__ float g_V[B_*H_*NM*DH];     // (b,h,m,d)
__device__ float g_O[B_*NQ*INNER];     // (b*n, h*96+d)
__device__ float g_X[B_*NQ*INNER];     // pre-LN

// ---------------- tf32 helpers ----------------
__device__ __forceinline__ unsigned f2t(float x) {
    unsigned r; asm("cvt.rna.tf32.f32 %0, %1;" : "=r"(r) : "f"(x)); return r;
}
__device__ __forceinline__ void splitt(float x, unsigned &hi, unsigned &lo) {
    hi = f2t(x);
    lo = f2t(x - __uint_as_float(hi));
}
__device__ __forceinline__ void mma8(float4 &c,
    unsigned a0, unsigned a1, unsigned a2, unsigned a3,
    unsigned b0, unsigned b1)
{
    asm("mma.sync.aligned.m16n8k8.row.col.f32.tf32.tf32.f32 "
        "{%0,%1,%2,%3},{%4,%5,%6,%7},{%8,%9},{%0,%1,%2,%3};"
        : "+f"(c.x), "+f"(c.y), "+f"(c.z), "+f"(c.w)
        : "r"(a0), "r"(a1), "r"(a2), "r"(a3), "r"(b0), "r"(b1));
}

// ---------------- cp.async helpers ----------------
__device__ __forceinline__ void cpa16(float* smem_dst, const float* gsrc) {
    unsigned s = (unsigned)__cvta_generic_to_shared(smem_dst);
    asm volatile("cp.async.cg.shared.global [%0], [%1], 16;\n" :: "r"(s), "l"(gsrc));
}
__device__ __forceinline__ void cpa_commit() {
    asm volatile("cp.async.commit_group;\n");
}
template<int N>
__device__ __forceinline__ void cpa_wait() {
    asm volatile("cp.async.wait_group %0;\n" :: "n"(N));
}

// ---------------- projection GEMM: C[M,768] = A[M,KD] @ W[KD,768] ----------------
// MODE 1: remap output to (b, h, s, d)     (Q/K/V projections)
// MODE 0: row-major + bias + residual       (output projection, pre-LN)
// SPLIT 1: split-tf32 (fp32-accurate, 3 MMAs/tile); SPLIT 0: single-pass tf32.
__device__ __forceinline__ void store_remap(float* out, int seqlen, int row, int c,
                                            float v0, float v1)
{
    int b = row / seqlen, s = row % seqlen;
    int h = c / DH, d = c % DH;            // c even -> pair stays in one head
    float* p = out + (((long)(b*H_ + h)*seqlen + s)*DH + d);
    p[0] = v0; p[1] = v1;
}

#define ASZ (128*36)
#define WSZ (32*72)
#define SMEM_GEMM ((2*ASZ + 2*WSZ)*4)

template<int KD, int MODE, int SPLIT>
__global__ void __launch_bounds__(256) gemm_proj(
    const float* __restrict__ A, const float* __restrict__ W,
    float* __restrict__ out, int seqlen,
    const float* __restrict__ bias, const float* __restrict__ resid)
{
    extern __shared__ float smg[];
    float* As = smg;               // [2][128*36]  128 rows x 32 k (stride 36)
    float* Ws = smg + 2*ASZ;       // [2][32*72]   32 k x 64 cols (stride 72)

    const int tid  = threadIdx.x;
    const int lane = tid & 31, warp = tid >> 5;
    const int g    = lane >> 2, tg = lane & 3;
    const int wr   = warp >> 1, wc = warp & 1;   // 4x2 warp grid, 32x32 each
    const long row0 = (long)blockIdx.x * 128;
    const int  col0 = blockIdx.y * 64;

    // per-thread load coords (fixed)
    const int lar = tid >> 3, lak = (tid & 7) * 4;   // A: row, k-offset
    const int lwk = tid >> 4, lwc = (tid & 15) * 4;  // W: k, col-offset

    float4 acc[2][4];
    #pragma unroll
    for (int i = 0; i < 2; i++)
        #pragma unroll
        for (int j = 0; j < 4; j++) acc[i][j] = make_float4(0.f,0.f,0.f,0.f);

    const int NK = KD / 32;

    // prefetch chunk 0 into buffer 0
    {
        #pragma unroll
        for (int i = 0; i < 4; i++) {
            int r = lar + 32*i;
            cpa16(&As[r*36 + lak], A + (row0 + r)*(long)KD + lak);
        }
        #pragma unroll
        for (int i = 0; i < 2; i++) {
            int kk = lwk + 16*i;
            cpa16(&Ws[kk*72 + lwc], W + (long)kk*768 + col0 + lwc);
        }
        cpa_commit();
    }

    for (int it = 0; it < NK; it++) {
        const int buf = it & 1;
        if (it + 1 < NK) {
            const int k0n = (it + 1) * 32;
            float* Ad = As + (buf^1)*ASZ;
            float* Wd = Ws + (buf^1)*WSZ;
            #pragma unroll
            for (int i = 0; i < 4; i++) {
                int r = lar + 32*i;
                cpa16(&Ad[r*36 + lak], A + (row0 + r)*(long)KD + k0n + lak);
            }
            #pragma unroll
            for (int i = 0; i < 2; i++) {
                int kk = lwk + 16*i;
                cpa16(&Wd[kk*72 + lwc], W + (long)(k0n + kk)*768 + col0 + lwc);
            }
            cpa_commit();
            cpa_wait<1>();
        } else {
            cpa_wait<0>();
        }
        __syncthreads();

        const float* Ab = As + buf*ASZ;
        const float* Wb = Ws + buf*WSZ;

        #pragma unroll
        for (int kk = 0; kk < 32; kk += 8) {
            unsigned ah[2][4], al[2][4];
            #pragma unroll
            for (int i = 0; i < 2; i++) {
                const float* p = &Ab[(wr*32 + i*16 + g)*36 + kk + tg];
                if constexpr (SPLIT) {
                    splitt(p[0],        ah[i][0], al[i][0]);
                    splitt(p[8*36],     ah[i][1], al[i][1]);
                    splitt(p[4],        ah[i][2], al[i][2]);
                    splitt(p[8*36+4],   ah[i][3], al[i][3]);
                } else {
                    ah[i][0] = f2t(p[0]);      ah[i][1] = f2t(p[8*36]);
                    ah[i][2] = f2t(p[4]);      ah[i][3] = f2t(p[8*36+4]);
                }
            }
            unsigned bh[4][2], bl[4][2];
            #pragma unroll
            for (int j = 0; j < 4; j++) {
                const float* p = &Wb[(kk + tg)*72 + wc*32 + j*8 + g];
                if constexpr (SPLIT) {
                    splitt(p[0],    bh[j][0], bl[j][0]);
                    splitt(p[4*72], bh[j][1], bl[j][1]);
                } else {
                    bh[j][0] = f2t(p[0]);
                    bh[j][1] = f2t(p[4*72]);
                }
            }
            #pragma unroll
            for (int i = 0; i < 2; i++)
                #pragma unroll
                for (int j = 0; j < 4; j++) {
                    mma8(acc[i][j], ah[i][0],ah[i][1],ah[i][2],ah[i][3], bh[j][0],bh[j][1]);
                    if constexpr (SPLIT) {
                        mma8(acc[i][j], ah[i][0],ah[i][1],ah[i][2],ah[i][3], bl[j][0],bl[j][1]);
                        mma8(acc[i][j], al[i][0],al[i][1],al[i][2],al[i][3], bh[j][0],bh[j][1]);
                    }
                }
        }
        __syncthreads();
    }

    #pragma unroll
    for (int i = 0; i < 2; i++) {
        int ra = (int)row0 + wr*32 + i*16 + g;
        int rb = ra + 8;
        #pragma unroll
        for (int j = 0; j < 4; j++) {
            int c = col0 + wc*32 + j*8 + 2*tg;
            if constexpr (MODE == 1) {
                store_remap(out, seqlen, ra, c, acc[i][j].x, acc[i][j].y);
                store_remap(out, seqlen, rb, c, acc[i][j].z, acc[i][j].w);
            } else {
                long i0 = (long)ra*768 + c;
                long i1 = (long)rb*768 + c;
                out[i0]   = acc[i][j].x + bias[c]   + resid[i0];
                out[i0+1] = acc[i][j].y + bias[c+1] + resid[i0+1];
                out[i1]   = acc[i][j].z + bias[c]   + resid[i1];
                out[i1+1] = acc[i][j].w + bias[c+1] + resid[i1+1];
            }
        }
    }
}

// ---------------- attention kernel ----------------
#define SS  1036
#define QS  108
#define KS2 108
#define SMEM_ATT ((32*SS + 32*QS + 128*KS2)*4)

__global__ void __launch_bounds__(256) attn_kernel(
    const int* __restrict__ dmask, const int* __restrict__ pmask,
    float* __restrict__ attn_out)
{
    extern __shared__ float sm[];
    float* S  = sm;                 // 32 x SS
    float* Qs = sm + 32*SS;         // 32 x QS
    float* Ks = Qs + 32*QS;         // 128 x KS2 (K chunk, later V chunk)

    const int tid  = threadIdx.x;
    const int lane = tid & 31, warp = tid >> 5;
    const int g    = lane >> 2, tg = lane & 3;
    const int b = blockIdx.z, h = blockIdx.y, n0 = blockIdx.x * 32;
    const int wr = warp >> 2, wc = warp & 3;    // 2x4 warp grid

    const float* Qg = g_Q + ((long)(b*H_ + h)*NQ + n0)*DH;
    const float* Kg = g_K + (long)(b*H_ + h)*NM*DH;
    const float* Vg = g_V + (long)(b*H_ + h)*NM*DH;

    // Q tile 32x96
    #pragma unroll
    for (int i = 0; i < 3; i++) {
        int q = tid + 256*i;
        int r = q / 24, c4 = q % 24;
        *(float4*)&Qs[r*QS + c4*4] = *(const float4*)(Qg + r*DH + c4*4);
    }

    // ---- S = Q K^T (split-tf32: feeds softmax, must stay fp32-accurate) ----
    for (int mc = 0; mc < 8; mc++) {
        __syncthreads();
        #pragma unroll
        for (int i = 0; i < 12; i++) {            // K chunk 128x96
            int q = tid + 256*i;
            int r = q / 24, c4 = q % 24;
            *(float4*)&Ks[r*KS2 + c4*4] = *(const float4*)(Kg + (long)(mc*128 + r)*DH + c4*4);
        }
        __syncthreads();

        float4 acc[4];
        #pragma unroll
        for (int j = 0; j < 4; j++) acc[j] = make_float4(0.f,0.f,0.f,0.f);

        #pragma unroll
        for (int kk = 0; kk < 96; kk += 8) {
            unsigned ah[4], al[4];
            {
                const float* p = &Qs[(wr*16 + g)*QS + kk + tg];
                splitt(p[0],       ah[0], al[0]);
                splitt(p[8*QS],    ah[1], al[1]);
                splitt(p[4],       ah[2], al[2]);
                splitt(p[8*QS+4],  ah[3], al[3]);
            }
            #pragma unroll
            for (int j = 0; j < 4; j++) {
                const float* p = &Ks[(wc*32 + j*8 + g)*KS2 + kk + tg];
                unsigned bh0, bl0, bh1, bl1;
                splitt(p[0], bh0, bl0);
                splitt(p[4], bh1, bl1);
                mma8(acc[j], ah[0],ah[1],ah[2],ah[3], bh0, bh1);
                mma8(acc[j], ah[0],ah[1],ah[2],ah[3], bl0, bl1);
                mma8(acc[j], al[0],al[1],al[2],al[3], bh0, bh1);
            }
        }
        int row = wr*16 + g;
        #pragma unroll
        for (int j = 0; j < 4; j++) {
            int c = mc*128 + wc*32 + j*8 + 2*tg;
            S[row*SS + c]       = acc[j].x;
            S[row*SS + c + 1]   = acc[j].y;
            S[(row+8)*SS + c]   = acc[j].z;
            S[(row+8)*SS + c+1] = acc[j].w;
        }
    }
    __syncthreads();

    // ---- mask + softmax (warp w handles rows 4w..4w+3), write attn ----
    for (int rr = 0; rr < 4; rr++) {
        int row = warp*4 + rr;
        bool dvalid = dmask[b*NQ + n0 + row] != 0;
        float* Sr = S + row*SS;
        float vbuf[32];
        float mx = -3.0e38f;
        #pragma unroll
        for (int i = 0; i < 32; i++) {
            int col = lane + 32*i;
            float vv = Sr[col] * SCALE;
            bool valid = dvalid && (pmask[b*NM + col] != 0);
            vv = valid ? vv : NEGV;
            vbuf[i] = vv;
            mx = fmaxf(mx, vv);
        }
        #pragma unroll
        for (int o = 16; o; o >>= 1) mx = fmaxf(mx, __shfl_xor_sync(~0u, mx, o));
        float sum = 0.f;
        #pragma unroll
        for (int i = 0; i < 32; i++) {
            float p = expf(vbuf[i] - mx);
            vbuf[i] = p; sum += p;
        }
        #pragma unroll
        for (int o = 16; o; o >>= 1) sum += __shfl_xor_sync(~0u, sum, o);
        float inv = 1.0f / sum;
        float* Ag = attn_out + ((long)(b*H_ + h)*NQ + n0 + row)*NM;
        #pragma unroll
        for (int i = 0; i < 32; i++) {
            int col = lane + 32*i;
            float p = vbuf[i] * inv;
            Sr[col] = p;
            Ag[col] = p;
        }
    }
    __syncthreads();

    // ---- O = P V  (single-pass tf32: error washed out by residual+LN) ----
    float4 oacc[3];
    #pragma unroll
    for (int j = 0; j < 3; j++) oacc[j] = make_float4(0.f,0.f,0.f,0.f);

    for (int mc = 0; mc < 8; mc++) {
        __syncthreads();
        #pragma unroll
        for (int i = 0; i < 12; i++) {            // V chunk 128x96 into Ks
            int q = tid + 256*i;
            int r = q / 24, c4 = q % 24;
            *(float4*)&Ks[r*KS2 + c4*4] = *(const float4*)(Vg + (long)(mc*128 + r)*DH + c4*4);
        }
        __syncthreads();

        #pragma unroll
        for (int kk = 0; kk < 128; kk += 8) {
            unsigned ah[4];
            {
                const float* p = &S[(wr*16 + g)*SS + mc*128 + kk + tg];
                ah[0] = f2t(p[0]);
                ah[1] = f2t(p[8*SS]);
                ah[2] = f2t(p[4]);
                ah[3] = f2t(p[8*SS+4]);
            }
            #pragma unroll
            for (int j = 0; j < 3; j++) {
                const float* p = &Ks[(kk + tg)*KS2 + wc*24 + j*8 + g];
                unsigned b0 = f2t(p[0]);
                unsigned b1 = f2t(p[4*KS2]);
                mma8(oacc[j], ah[0],ah[1],ah[2],ah[3], b0, b1);
            }
        }
    }

    // store O: g_O[(b*NQ + n)*INNER + h*96 + d]
    {
        int ra = wr*16 + g, rb = ra + 8;
        #pragma unroll
        for (int j = 0; j < 3; j++) {
            int c = wc*24 + j*8 + 2*tg;
            long i0 = ((long)b*NQ + n0 + ra)*INNER + h*DH + c;
            long i1 = ((long)b*NQ + n0 + rb)*INNER + h*DH + c;
            g_O[i0]   = oacc[j].x;  g_O[i0+1] = oacc[j].y;
            g_O[i1]   = oacc[j].z;  g_O[i1+1] = oacc[j].w;
        }
    }
}

// ---------------- LayerNorm: warp per row ----------------
__global__ void __launch_bounds__(256) ln_kernel(
    const float* __restrict__ X, const float* __restrict__ gamma,
    const float* __restrict__ beta, float* __restrict__ out)
{
    int row  = blockIdx.x * 8 + (threadIdx.x >> 5);
    int lane = threadIdx.x & 31;
    const float* x = X + (long)row * INNER;
    float v[24];
    float s = 0.f;
    #pragma unroll
    for (int i = 0; i < 24; i++) { v[i] = x[lane + 32*i]; s += v[i]; }
    #pragma unroll
    for (int o = 16; o; o >>= 1) s += __shfl_xor_sync(~0u, s, o);
    float mu = s * (1.0f/INNER);
    float q = 0.f;
    #pragma unroll
    for (int i = 0; i < 24; i++) { float d = v[i] - mu; q += d*d; }
    #pragma unroll
    for (int o = 16; o; o >>= 1) q += __shfl_xor_sync(~0u, q, o);
    float inv = rsqrtf(q * (1.0f/INNER) + 1e-5f);
    float* op = out + (long)row * INNER;
    #pragma unroll
    for (int i = 0; i < 24; i++) {
        int c = lane + 32*i;
        op[c] = (v[i] - mu) * inv * gamma[c] + beta[c];
    }
}

// ---------------- launch ----------------
extern "C" void kernel_launch(void* const* d_in, const int* in_sizes, int n_in,
                              void* d_out, int out_size)
{
    const float* drug   = (const float*)d_in[0];
    const float* target = (const float*)d_in[1];
    const int*   dmask  = (const int*)d_in[2];
    const int*   pmask  = (const int*)d_in[3];
    const float* Wq = (const float*)d_in[4];
    const float* Wk = (const float*)d_in[5];
    const float* Wv = (const float*)d_in[6];
    const float* Wo = (const float*)d_in[7];
    const float* bo = (const float*)d_in[8];
    const float* gamma = (const float*)d_in[9];
    const float* beta  = (const float*)d_in[10];

    float* out  = (float*)d_out;
    float* attn = out + (long)OUT_ELEMS;   // tuple (out, attn) concatenated

    float *Qp, *Kp, *Vp, *Op, *Xp;
    cudaGetSymbolAddress((void**)&Qp, g_Q);
    cudaGetSymbolAddress((void**)&Kp, g_K);
    cudaGetSymbolAddress((void**)&Vp, g_V);
    cudaGetSymbolAddress((void**)&Op, g_O);
    cudaGetSymbolAddress((void**)&Xp, g_X);

    cudaFuncSetAttribute(gemm_proj<DD,1,1>,    cudaFuncAttributeMaxDynamicSharedMemorySize, SMEM_GEMM);
    cudaFuncSetAttribute(gemm_proj<DT,1,1>,    cudaFuncAttributeMaxDynamicSharedMemorySize, SMEM_GEMM);
    cudaFuncSetAttribute(gemm_proj<DT,1,0>,    cudaFuncAttributeMaxDynamicSharedMemorySize, SMEM_GEMM);
    cudaFuncSetAttribute(gemm_proj<INNER,0,0>, cudaFuncAttributeMaxDynamicSharedMemorySize, SMEM_GEMM);
    cudaFuncSetAttribute(attn_kernel,          cudaFuncAttributeMaxDynamicSharedMemorySize, SMEM_ATT);

    // Q/K projections: split-tf32 (feed softmax). V projection: single-pass tf32.
    gemm_proj<DD,1,1><<<dim3(B_*NQ/128, 768/64), 256, SMEM_GEMM>>>(drug,   Wq, Qp, NQ, nullptr, nullptr);
    gemm_proj<DT,1,1><<<dim3(B_*NM/128, 768/64), 256, SMEM_GEMM>>>(target, Wk, Kp, NM, nullptr, nullptr);
    gemm_proj<DT,1,0><<<dim3(B_*NM/128, 768/64), 256, SMEM_GEMM>>>(target, Wv, Vp, NM, nullptr, nullptr);

    // attention (scores + mask + softmax + attn out + P@V)
    attn_kernel<<<dim3(NQ/32, H_, B_), 256, SMEM_ATT>>>(dmask, pmask, attn);

    // output projection + bias + residual (single-pass tf32)
    gemm_proj<INNER,0,0><<<dim3(B_*NQ/128, 768/64), 256, SMEM_GEMM>>>(Op, Wo, Xp, NQ, bo, drug);

    // LayerNorm
    ln_kernel<<<B_*NQ/8, 256>>>(Xp, gamma, beta, out);
}